// round 1
// baseline (speedup 1.0000x reference)
#include <cuda_runtime.h>
#include <cuda_bf16.h>
#include <math.h>

// Problem constants
#define N_TOK 2048
#define M_TOK 2048
#define D_DIM 1024
#define C_DIM 768
#define H_HEADS 16
#define HD_DIM 64
#define FF_DIM 4096

// ---------------------------------------------------------------------------
// Scratch (static device globals; no runtime allocation allowed)
// ---------------------------------------------------------------------------
__device__ float g_xq[N_TOK * D_DIM];          // LN(x)
__device__ float g_kv[M_TOK * C_DIM];          // LN(ctx)
__device__ float g_q [N_TOK * D_DIM];
__device__ float g_k [M_TOK * D_DIM];
__device__ float g_v [M_TOK * D_DIM];
__device__ float g_s [(size_t)H_HEADS * N_TOK * M_TOK];   // 256 MB scores
__device__ float g_o [N_TOK * D_DIM];          // attn out (head-merged)
__device__ float g_x1[N_TOK * D_DIM];          // after o-proj + residual
__device__ float g_hl[N_TOK * D_DIM];          // LN(x1)
__device__ float g_h1[N_TOK * FF_DIM];         // gelu(mlp1)

// ---------------------------------------------------------------------------
// Helpers
// ---------------------------------------------------------------------------
__device__ __forceinline__ float gelu_tanh(float x) {
    const float k0 = 0.7978845608028654f;   // sqrt(2/pi)
    float x3 = x * x * x;
    return 0.5f * x * (1.0f + tanhf(k0 * (x + 0.044715f * x3)));
}

__device__ __forceinline__ float blockReduceSum(float v) {
    __shared__ float s[32];
    __syncthreads();
    int lane = threadIdx.x & 31, wid = threadIdx.x >> 5;
    #pragma unroll
    for (int o = 16; o > 0; o >>= 1) v += __shfl_down_sync(0xffffffffu, v, o);
    if (lane == 0) s[wid] = v;
    __syncthreads();
    int nw = (blockDim.x + 31) >> 5;
    v = (threadIdx.x < nw) ? s[threadIdx.x] : 0.0f;
    if (wid == 0) {
        #pragma unroll
        for (int o = 16; o > 0; o >>= 1) v += __shfl_down_sync(0xffffffffu, v, o);
        if (lane == 0) s[0] = v;
    }
    __syncthreads();
    return s[0];
}

__device__ __forceinline__ float blockReduceMax(float v) {
    __shared__ float s[32];
    __syncthreads();
    int lane = threadIdx.x & 31, wid = threadIdx.x >> 5;
    #pragma unroll
    for (int o = 16; o > 0; o >>= 1) v = fmaxf(v, __shfl_down_sync(0xffffffffu, v, o));
    if (lane == 0) s[wid] = v;
    __syncthreads();
    int nw = (blockDim.x + 31) >> 5;
    v = (threadIdx.x < nw) ? s[threadIdx.x] : -INFINITY;
    if (wid == 0) {
        #pragma unroll
        for (int o = 16; o > 0; o >>= 1) v = fmaxf(v, __shfl_down_sync(0xffffffffu, v, o));
        if (lane == 0) s[0] = v;
    }
    __syncthreads();
    return s[0];
}

// ---------------------------------------------------------------------------
// LayerNorm: one block per row
// ---------------------------------------------------------------------------
__global__ void layernorm_kernel(const float* __restrict__ in,
                                 const float* __restrict__ w,
                                 const float* __restrict__ b,
                                 float* __restrict__ out, int cols)
{
    long row = blockIdx.x;
    const float* x = in + row * cols;
    float sum = 0.0f, sumsq = 0.0f;
    for (int i = threadIdx.x; i < cols; i += blockDim.x) {
        float v = x[i];
        sum += v;
        sumsq += v * v;
    }
    float tsum = blockReduceSum(sum);
    float tsq  = blockReduceSum(sumsq);
    float mean = tsum / cols;
    float var  = tsq / cols - mean * mean;
    float rstd = rsqrtf(var + 1e-12f);
    float* o = out + row * cols;
    for (int i = threadIdx.x; i < cols; i += blockDim.x) {
        o[i] = (x[i] - mean) * rstd * w[i] + b[i];
    }
}

// ---------------------------------------------------------------------------
// Row softmax over 2048 columns, row cached in smem
// ---------------------------------------------------------------------------
__global__ void softmax_kernel(float* __restrict__ s, int cols)
{
    extern __shared__ float rowbuf[];
    size_t row = blockIdx.x;
    float* p = s + row * (size_t)cols;

    float mx = -INFINITY;
    for (int i = threadIdx.x; i < cols; i += blockDim.x) {
        float v = p[i];
        rowbuf[i] = v;
        mx = fmaxf(mx, v);
    }
    mx = blockReduceMax(mx);

    float sum = 0.0f;
    for (int i = threadIdx.x; i < cols; i += blockDim.x) {
        float e = __expf(rowbuf[i] - mx);
        rowbuf[i] = e;
        sum += e;
    }
    sum = blockReduceSum(sum);
    float inv = 1.0f / sum;
    for (int i = threadIdx.x; i < cols; i += blockDim.x) {
        p[i] = rowbuf[i] * inv;
    }
}

// ---------------------------------------------------------------------------
// Generic tiled SGEMM: C[M,N] = alpha * A[M,K] @ op(B) (+bias)(gelu)(+res)
// TRANSB: B stored [N,K] row-major (used for Q K^T).
// Strided batching via grid.z. All dims assumed divisible by tile sizes
// (verified for every call site in this problem).
// ---------------------------------------------------------------------------
template<int BM, int BN, int BK, int TM, int TN,
         bool TRANSB, bool BIAS, bool GELU, bool RES>
__global__ __launch_bounds__(256)
void sgemm_kernel(const float* __restrict__ A, const float* __restrict__ B,
                  const float* __restrict__ bias, const float* __restrict__ res,
                  float* __restrict__ C,
                  int Ndim, int Kdim,
                  int lda, int ldb, int ldc,
                  long strideA, long strideB, long strideC,
                  float alpha)
{
    A += (long)blockIdx.z * strideA;
    B += (long)blockIdx.z * strideB;
    C += (long)blockIdx.z * strideC;

    const int m0 = blockIdx.y * BM;
    const int n0 = blockIdx.x * BN;

    __shared__ float As[BK][BM];
    __shared__ float Bs[BK][BN];

    const int tid = threadIdx.x;
    constexpr int CN = BN / TN;       // thread cols
    const int tx = tid % CN;
    const int ty = tid / CN;

    float acc[TM][TN];
    #pragma unroll
    for (int i = 0; i < TM; i++)
        #pragma unroll
        for (int j = 0; j < TN; j++) acc[i][j] = 0.0f;

    for (int k0 = 0; k0 < Kdim; k0 += BK) {
        // A tile: [BM x BK] -> As[k][m]
        #pragma unroll 2
        for (int i = tid; i < BM * BK / 4; i += 256) {
            int m  = i / (BK / 4);
            int kq = (i % (BK / 4)) * 4;
            float4 v = *reinterpret_cast<const float4*>(
                &A[(long)(m0 + m) * lda + k0 + kq]);
            As[kq + 0][m] = v.x; As[kq + 1][m] = v.y;
            As[kq + 2][m] = v.z; As[kq + 3][m] = v.w;
        }
        // B tile
        if (!TRANSB) {
            #pragma unroll 2
            for (int i = tid; i < BK * BN / 4; i += 256) {
                int kk = i / (BN / 4);
                int n  = (i % (BN / 4)) * 4;
                float4 v = *reinterpret_cast<const float4*>(
                    &B[(long)(k0 + kk) * ldb + n0 + n]);
                *reinterpret_cast<float4*>(&Bs[kk][n]) = v;
            }
        } else {
            #pragma unroll 2
            for (int i = tid; i < BN * BK / 4; i += 256) {
                int n  = i / (BK / 4);
                int kq = (i % (BK / 4)) * 4;
                float4 v = *reinterpret_cast<const float4*>(
                    &B[(long)(n0 + n) * ldb + k0 + kq]);
                Bs[kq + 0][n] = v.x; Bs[kq + 1][n] = v.y;
                Bs[kq + 2][n] = v.z; Bs[kq + 3][n] = v.w;
            }
        }
        __syncthreads();

        #pragma unroll
        for (int kk = 0; kk < BK; kk++) {
            float a[TM], b[TN];
            #pragma unroll
            for (int i = 0; i < TM; i++) a[i] = As[kk][ty * TM + i];
            #pragma unroll
            for (int j = 0; j < TN; j++) b[j] = Bs[kk][tx * TN + j];
            #pragma unroll
            for (int i = 0; i < TM; i++)
                #pragma unroll
                for (int j = 0; j < TN; j++)
                    acc[i][j] += a[i] * b[j];
        }
        __syncthreads();
    }

    // Epilogue
    #pragma unroll
    for (int i = 0; i < TM; i++) {
        long row = m0 + ty * TM + i;
        #pragma unroll
        for (int j = 0; j < TN; j++) {
            int col = n0 + tx * TN + j;
            float v = acc[i][j] * alpha;
            if (BIAS) v += bias[col];
            if (GELU) v = gelu_tanh(v);
            if (RES)  v += res[row * ldc + col];
            C[row * ldc + col] = v;
        }
    }
}

// ---------------------------------------------------------------------------
// Launch
// ---------------------------------------------------------------------------
extern "C" void kernel_launch(void* const* d_in, const int* in_sizes, int n_in,
                              void* d_out, int out_size)
{
    const float* x    = (const float*)d_in[0];
    const float* ctx  = (const float*)d_in[1];
    const float* wq   = (const float*)d_in[2];
    const float* bq   = (const float*)d_in[3];
    const float* wk   = (const float*)d_in[4];
    const float* bk   = (const float*)d_in[5];
    const float* wv   = (const float*)d_in[6];
    const float* bv   = (const float*)d_in[7];
    const float* wo   = (const float*)d_in[8];
    const float* bo   = (const float*)d_in[9];
    const float* w1   = (const float*)d_in[10];
    const float* b1   = (const float*)d_in[11];
    const float* w2   = (const float*)d_in[12];
    const float* b2   = (const float*)d_in[13];
    const float* qn_w = (const float*)d_in[14];
    const float* qn_b = (const float*)d_in[15];
    const float* kvn_w= (const float*)d_in[16];
    const float* kvn_b= (const float*)d_in[17];
    const float* pn_w = (const float*)d_in[18];
    const float* pn_b = (const float*)d_in[19];
    float* out = (float*)d_out;

    float *xq, *kv, *q, *k, *v, *s, *o, *x1, *hl, *h1;
    cudaGetSymbolAddress((void**)&xq, g_xq);
    cudaGetSymbolAddress((void**)&kv, g_kv);
    cudaGetSymbolAddress((void**)&q,  g_q);
    cudaGetSymbolAddress((void**)&k,  g_k);
    cudaGetSymbolAddress((void**)&v,  g_v);
    cudaGetSymbolAddress((void**)&s,  g_s);
    cudaGetSymbolAddress((void**)&o,  g_o);
    cudaGetSymbolAddress((void**)&x1, g_x1);
    cudaGetSymbolAddress((void**)&hl, g_hl);
    cudaGetSymbolAddress((void**)&h1, g_h1);

    const float inv_scale = 1.0f / 8.0f;   // 1/sqrt(HD=64)

    // 1) pre-norms
    layernorm_kernel<<<N_TOK, 256>>>(x,   qn_w,  qn_b,  xq, D_DIM);
    layernorm_kernel<<<M_TOK, 256>>>(ctx, kvn_w, kvn_b, kv, C_DIM);

    // 2) Q = xq @ wq + bq   [2048,1024]x[1024,1024]
    {
        dim3 g(D_DIM / 128, N_TOK / 128, 1);
        sgemm_kernel<128,128,16,8,8,false,true,false,false><<<g, 256>>>(
            xq, wq, bq, nullptr, q, D_DIM, D_DIM,
            D_DIM, D_DIM, D_DIM, 0, 0, 0, 1.0f);
    }
    // 3) K = kv @ wk + bk   [2048,768]x[768,1024]
    {
        dim3 g(D_DIM / 128, M_TOK / 128, 1);
        sgemm_kernel<128,128,16,8,8,false,true,false,false><<<g, 256>>>(
            kv, wk, bk, nullptr, k, D_DIM, C_DIM,
            C_DIM, D_DIM, D_DIM, 0, 0, 0, 1.0f);
    }
    // 4) V = kv @ wv + bv
    {
        dim3 g(D_DIM / 128, M_TOK / 128, 1);
        sgemm_kernel<128,128,16,8,8,false,true,false,false><<<g, 256>>>(
            kv, wv, bv, nullptr, v, D_DIM, C_DIM,
            C_DIM, D_DIM, D_DIM, 0, 0, 0, 1.0f);
    }
    // 5) S[h] = (Q_h @ K_h^T) / 8      batched over 16 heads
    {
        dim3 g(M_TOK / 128, N_TOK / 128, H_HEADS);
        sgemm_kernel<128,128,16,8,8,true,false,false,false><<<g, 256>>>(
            q, k, nullptr, nullptr, s, M_TOK, HD_DIM,
            D_DIM, D_DIM, M_TOK,
            HD_DIM, HD_DIM, (long)N_TOK * M_TOK, inv_scale);
    }
    // 6) softmax rows
    softmax_kernel<<<H_HEADS * N_TOK, 256, M_TOK * sizeof(float)>>>(s, M_TOK);

    // 7) O_h = P_h @ V_h               batched, N=64 tile variant
    {
        dim3 g(HD_DIM / 64, N_TOK / 128, H_HEADS);
        sgemm_kernel<128,64,16,8,4,false,false,false,false><<<g, 256>>>(
            s, v, nullptr, nullptr, o, HD_DIM, M_TOK,
            M_TOK, D_DIM, D_DIM,
            (long)N_TOK * M_TOK, HD_DIM, HD_DIM, 1.0f);
    }
    // 8) x1 = o @ wo + bo + x
    {
        dim3 g(D_DIM / 128, N_TOK / 128, 1);
        sgemm_kernel<128,128,16,8,8,false,true,false,true><<<g, 256>>>(
            o, wo, bo, x, x1, D_DIM, D_DIM,
            D_DIM, D_DIM, D_DIM, 0, 0, 0, 1.0f);
    }
    // 9) hl = LN(x1)
    layernorm_kernel<<<N_TOK, 256>>>(x1, pn_w, pn_b, hl, D_DIM);

    // 10) h1 = gelu(hl @ w1 + b1)   [2048,1024]x[1024,4096]
    {
        dim3 g(FF_DIM / 128, N_TOK / 128, 1);
        sgemm_kernel<128,128,16,8,8,false,true,true,false><<<g, 256>>>(
            hl, w1, b1, nullptr, h1, FF_DIM, D_DIM,
            D_DIM, FF_DIM, FF_DIM, 0, 0, 0, 1.0f);
    }
    // 11) out = h1 @ w2 + b2 + x1   [2048,4096]x[4096,1024]
    {
        dim3 g(D_DIM / 128, N_TOK / 128, 1);
        sgemm_kernel<128,128,16,8,8,false,true,false,true><<<g, 256>>>(
            h1, w2, b2, x1, out, D_DIM, FF_DIM,
            FF_DIM, D_DIM, D_DIM, 0, 0, 0, 1.0f);
    }
}

// round 6
// speedup vs baseline: 2.3569x; 2.3569x over previous
#include <cuda_runtime.h>
#include <cuda_bf16.h>
#include <math.h>
#include <stdint.h>

// Problem constants
#define N_TOK 2048
#define M_TOK 2048
#define D_DIM 1024
#define C_DIM 768
#define H_HEADS 16
#define HD_DIM 64
#define FF_DIM 4096

// ---------------------------------------------------------------------------
// Scratch (static device globals; no runtime allocation allowed)
// ---------------------------------------------------------------------------
__device__ float g_xq[N_TOK * D_DIM];
__device__ float g_kv[M_TOK * C_DIM];
__device__ float g_q [N_TOK * D_DIM];
__device__ float g_k [M_TOK * D_DIM];
__device__ float g_v [M_TOK * D_DIM];
__device__ float g_s [(size_t)H_HEADS * N_TOK * M_TOK];
__device__ float g_o [N_TOK * D_DIM];
__device__ float g_x1[N_TOK * D_DIM];
__device__ float g_hl[N_TOK * D_DIM];
__device__ float g_h1[N_TOK * FF_DIM];

// ---------------------------------------------------------------------------
// Helpers
// ---------------------------------------------------------------------------
__device__ __forceinline__ float gelu_tanh(float x) {
    const float k0 = 0.7978845608028654f;
    float x3 = x * x * x;
    return 0.5f * x * (1.0f + tanhf(k0 * (x + 0.044715f * x3)));
}

__device__ __forceinline__ float to_tf32(float x) {
    uint32_t t;
    asm("cvt.rna.tf32.f32 %0, %1;" : "=r"(t) : "f"(x));
    return __uint_as_float(t);
}

__device__ __forceinline__ void mma_tf32(float c[4], const uint32_t a[4],
                                         const uint32_t b[2]) {
    asm volatile(
        "mma.sync.aligned.m16n8k8.row.col.f32.tf32.tf32.f32 "
        "{%0,%1,%2,%3}, {%4,%5,%6,%7}, {%8,%9}, {%0,%1,%2,%3};"
        : "+f"(c[0]), "+f"(c[1]), "+f"(c[2]), "+f"(c[3])
        : "r"(a[0]), "r"(a[1]), "r"(a[2]), "r"(a[3]), "r"(b[0]), "r"(b[1]));
}

__device__ __forceinline__ float blockReduceSum(float v) {
    __shared__ float s[32];
    __syncthreads();
    int lane = threadIdx.x & 31, wid = threadIdx.x >> 5;
    #pragma unroll
    for (int o = 16; o > 0; o >>= 1) v += __shfl_down_sync(0xffffffffu, v, o);
    if (lane == 0) s[wid] = v;
    __syncthreads();
    int nw = (blockDim.x + 31) >> 5;
    v = (threadIdx.x < nw) ? s[threadIdx.x] : 0.0f;
    if (wid == 0) {
        #pragma unroll
        for (int o = 16; o > 0; o >>= 1) v += __shfl_down_sync(0xffffffffu, v, o);
        if (lane == 0) s[0] = v;
    }
    __syncthreads();
    return s[0];
}

__device__ __forceinline__ float blockReduceMax(float v) {
    __shared__ float s[32];
    __syncthreads();
    int lane = threadIdx.x & 31, wid = threadIdx.x >> 5;
    #pragma unroll
    for (int o = 16; o > 0; o >>= 1) v = fmaxf(v, __shfl_down_sync(0xffffffffu, v, o));
    if (lane == 0) s[wid] = v;
    __syncthreads();
    int nw = (blockDim.x + 31) >> 5;
    v = (threadIdx.x < nw) ? s[threadIdx.x] : -INFINITY;
    if (wid == 0) {
        #pragma unroll
        for (int o = 16; o > 0; o >>= 1) v = fmaxf(v, __shfl_down_sync(0xffffffffu, v, o));
        if (lane == 0) s[0] = v;
    }
    __syncthreads();
    return s[0];
}

// ---------------------------------------------------------------------------
// LayerNorm: one block per row
// ---------------------------------------------------------------------------
__global__ void layernorm_kernel(const float* __restrict__ in,
                                 const float* __restrict__ w,
                                 const float* __restrict__ b,
                                 float* __restrict__ out, int cols)
{
    long row = blockIdx.x;
    const float* x = in + row * cols;
    float sum = 0.0f, sumsq = 0.0f;
    for (int i = threadIdx.x; i < cols; i += blockDim.x) {
        float v = x[i];
        sum += v;
        sumsq += v * v;
    }
    float tsum = blockReduceSum(sum);
    float tsq  = blockReduceSum(sumsq);
    float mean = tsum / cols;
    float var  = tsq / cols - mean * mean;
    float rstd = rsqrtf(var + 1e-12f);
    float* o = out + row * cols;
    for (int i = threadIdx.x; i < cols; i += blockDim.x) {
        o[i] = (x[i] - mean) * rstd * w[i] + b[i];
    }
}

// ---------------------------------------------------------------------------
// Row softmax over 2048 columns, row cached in smem
// ---------------------------------------------------------------------------
__global__ void softmax_kernel(float* __restrict__ s, int cols)
{
    extern __shared__ float rowbuf[];
    size_t row = blockIdx.x;
    float* p = s + row * (size_t)cols;

    float mx = -INFINITY;
    for (int i = threadIdx.x; i < cols; i += blockDim.x) {
        float v = p[i];
        rowbuf[i] = v;
        mx = fmaxf(mx, v);
    }
    mx = blockReduceMax(mx);

    float sum = 0.0f;
    for (int i = threadIdx.x; i < cols; i += blockDim.x) {
        float e = __expf(rowbuf[i] - mx);
        rowbuf[i] = e;
        sum += e;
    }
    sum = blockReduceSum(sum);
    float inv = 1.0f / sum;
    for (int i = threadIdx.x; i < cols; i += blockDim.x) {
        p[i] = rowbuf[i] * inv;
    }
}

// ---------------------------------------------------------------------------
// tf32 tensor-core GEMM: C[M,N] = alpha * A[M,K] @ op(B) (+bias)(gelu)(+res)
//   - A row-major [M,K]. TRANSB: B stored [N,K] row-major, else [K,N].
//   - 256 threads = 8 warps, warp grid WARPS_M x WARPS_N.
//   - m16n8k8 tf32 HMMA, fp32 accumulate.
// Bank-conflict-free fragment loads:
//   As[m][BK+4]  (stride 36 words): a-frag bank = 4*group + tig  (bijective)
//   Bs[k][BN+8]  (stride BN+8, BN%32==0, pad 8): bank = 8*tig + group
//   Bs[n][BK+4]  (TRANSB): same pattern as A.
// ---------------------------------------------------------------------------
template<int BM, int BN, int BK, int WARPS_M, int WARPS_N,
         bool TRANSB, bool BIAS, bool GELU, bool RES>
__global__ __launch_bounds__(256)
void mma_gemm(const float* __restrict__ A, const float* __restrict__ B,
              const float* __restrict__ bias, const float* __restrict__ res,
              float* __restrict__ C,
              int Kdim, int lda, int ldb, int ldc,
              long strideA, long strideB, long strideC,
              float alpha)
{
    A += (long)blockIdx.z * strideA;
    B += (long)blockIdx.z * strideB;
    C += (long)blockIdx.z * strideC;

    constexpr int WM = BM / WARPS_M;     // warp tile m
    constexpr int WN = BN / WARPS_N;     // warp tile n
    constexpr int MT = WM / 16;          // m16 tiles per warp
    constexpr int NT = WN / 8;           // n8 tiles per warp

    const int m0 = blockIdx.y * BM;
    const int n0 = blockIdx.x * BN;

    __shared__ float As[BM][BK + 4];
    constexpr int BS_R = TRANSB ? BN : BK;
    constexpr int BS_C = TRANSB ? (BK + 4) : (BN + 8);
    __shared__ float Bs[BS_R][BS_C];

    const int tid  = threadIdx.x;
    const int warp = tid >> 5;
    const int lane = tid & 31;
    const int grp  = lane >> 2;          // 0..7
    const int tig  = lane & 3;           // 0..3
    const int wm0  = (warp / WARPS_N) * WM;
    const int wn0  = (warp % WARPS_N) * WN;

    float acc[MT][NT][4];
    #pragma unroll
    for (int i = 0; i < MT; i++)
        #pragma unroll
        for (int j = 0; j < NT; j++)
            #pragma unroll
            for (int r = 0; r < 4; r++) acc[i][j][r] = 0.0f;

    constexpr int A_V4 = BM * BK / 4;             // float4 loads for A tile
    constexpr int B_V4 = (TRANSB ? BN * BK : BK * BN) / 4;

    for (int k0 = 0; k0 < Kdim; k0 += BK) {
        // --- A tile: [BM x BK], coalesced float4 along k, cvt to tf32 ---
        #pragma unroll
        for (int it = 0; it < A_V4 / 256; it++) {
            int i  = tid + it * 256;
            int m  = i / (BK / 4);
            int kq = (i % (BK / 4)) * 4;
            float4 v = *reinterpret_cast<const float4*>(
                &A[(long)(m0 + m) * lda + k0 + kq]);
            v.x = to_tf32(v.x); v.y = to_tf32(v.y);
            v.z = to_tf32(v.z); v.w = to_tf32(v.w);
            *reinterpret_cast<float4*>(&As[m][kq]) = v;
        }
        // --- B tile ---
        if (TRANSB) {
            #pragma unroll
            for (int it = 0; it < B_V4 / 256; it++) {
                int i  = tid + it * 256;
                int n  = i / (BK / 4);
                int kq = (i % (BK / 4)) * 4;
                float4 v = *reinterpret_cast<const float4*>(
                    &B[(long)(n0 + n) * ldb + k0 + kq]);
                v.x = to_tf32(v.x); v.y = to_tf32(v.y);
                v.z = to_tf32(v.z); v.w = to_tf32(v.w);
                *reinterpret_cast<float4*>(&Bs[n][kq]) = v;
            }
        } else {
            #pragma unroll
            for (int it = 0; it < B_V4 / 256; it++) {
                int i  = tid + it * 256;
                int kk = i / (BN / 4);
                int n  = (i % (BN / 4)) * 4;
                float4 v = *reinterpret_cast<const float4*>(
                    &B[(long)(k0 + kk) * ldb + n0 + n]);
                v.x = to_tf32(v.x); v.y = to_tf32(v.y);
                v.z = to_tf32(v.z); v.w = to_tf32(v.w);
                *reinterpret_cast<float4*>(&Bs[kk][n]) = v;
            }
        }
        __syncthreads();

        // --- compute: BK/8 mma k-steps ---
        #pragma unroll
        for (int ks = 0; ks < BK / 8; ks++) {
            const int kb = ks * 8;
            uint32_t af[MT][4];
            #pragma unroll
            for (int mi = 0; mi < MT; mi++) {
                int r = wm0 + mi * 16 + grp;
                af[mi][0] = __float_as_uint(As[r    ][kb + tig    ]);
                af[mi][1] = __float_as_uint(As[r + 8][kb + tig    ]);
                af[mi][2] = __float_as_uint(As[r    ][kb + tig + 4]);
                af[mi][3] = __float_as_uint(As[r + 8][kb + tig + 4]);
            }
            uint32_t bf[NT][2];
            #pragma unroll
            for (int ni = 0; ni < NT; ni++) {
                int c = wn0 + ni * 8 + grp;
                if (TRANSB) {
                    bf[ni][0] = __float_as_uint(Bs[c][kb + tig    ]);
                    bf[ni][1] = __float_as_uint(Bs[c][kb + tig + 4]);
                } else {
                    bf[ni][0] = __float_as_uint(Bs[kb + tig    ][c]);
                    bf[ni][1] = __float_as_uint(Bs[kb + tig + 4][c]);
                }
            }
            #pragma unroll
            for (int mi = 0; mi < MT; mi++)
                #pragma unroll
                for (int ni = 0; ni < NT; ni++)
                    mma_tf32(acc[mi][ni], af[mi], bf[ni]);
        }
        __syncthreads();
    }

    // --- epilogue ---
    #pragma unroll
    for (int mi = 0; mi < MT; mi++) {
        #pragma unroll
        for (int ni = 0; ni < NT; ni++) {
            long r0 = m0 + wm0 + mi * 16 + grp;
            long r1 = r0 + 8;
            int  c0 = n0 + wn0 + ni * 8 + tig * 2;
            float v0 = acc[mi][ni][0] * alpha;
            float v1 = acc[mi][ni][1] * alpha;
            float v2 = acc[mi][ni][2] * alpha;
            float v3 = acc[mi][ni][3] * alpha;
            if (BIAS) {
                float bb0 = bias[c0], bb1 = bias[c0 + 1];
                v0 += bb0; v1 += bb1; v2 += bb0; v3 += bb1;
            }
            if (GELU) {
                v0 = gelu_tanh(v0); v1 = gelu_tanh(v1);
                v2 = gelu_tanh(v2); v3 = gelu_tanh(v3);
            }
            if (RES) {
                const float2 r0v = *reinterpret_cast<const float2*>(&res[r0 * ldc + c0]);
                const float2 r1v = *reinterpret_cast<const float2*>(&res[r1 * ldc + c0]);
                v0 += r0v.x; v1 += r0v.y; v2 += r1v.x; v3 += r1v.y;
            }
            *reinterpret_cast<float2*>(&C[r0 * ldc + c0]) = make_float2(v0, v1);
            *reinterpret_cast<float2*>(&C[r1 * ldc + c0]) = make_float2(v2, v3);
        }
    }
}

// ---------------------------------------------------------------------------
// Launch
// ---------------------------------------------------------------------------
extern "C" void kernel_launch(void* const* d_in, const int* in_sizes, int n_in,
                              void* d_out, int out_size)
{
    const float* x    = (const float*)d_in[0];
    const float* ctx  = (const float*)d_in[1];
    const float* wq   = (const float*)d_in[2];
    const float* bq   = (const float*)d_in[3];
    const float* wk   = (const float*)d_in[4];
    const float* bk   = (const float*)d_in[5];
    const float* wv   = (const float*)d_in[6];
    const float* bv   = (const float*)d_in[7];
    const float* wo   = (const float*)d_in[8];
    const float* bo   = (const float*)d_in[9];
    const float* w1   = (const float*)d_in[10];
    const float* b1   = (const float*)d_in[11];
    const float* w2   = (const float*)d_in[12];
    const float* b2   = (const float*)d_in[13];
    const float* qn_w = (const float*)d_in[14];
    const float* qn_b = (const float*)d_in[15];
    const float* kvn_w= (const float*)d_in[16];
    const float* kvn_b= (const float*)d_in[17];
    const float* pn_w = (const float*)d_in[18];
    const float* pn_b = (const float*)d_in[19];
    float* out = (float*)d_out;

    float *xq, *kv, *q, *k, *v, *s, *o, *x1, *hl, *h1;
    cudaGetSymbolAddress((void**)&xq, g_xq);
    cudaGetSymbolAddress((void**)&kv, g_kv);
    cudaGetSymbolAddress((void**)&q,  g_q);
    cudaGetSymbolAddress((void**)&k,  g_k);
    cudaGetSymbolAddress((void**)&v,  g_v);
    cudaGetSymbolAddress((void**)&s,  g_s);
    cudaGetSymbolAddress((void**)&o,  g_o);
    cudaGetSymbolAddress((void**)&x1, g_x1);
    cudaGetSymbolAddress((void**)&hl, g_hl);
    cudaGetSymbolAddress((void**)&h1, g_h1);

    const float inv_scale = 1.0f / 8.0f;   // 1/sqrt(64)

    // 1) pre-norms
    layernorm_kernel<<<N_TOK, 256>>>(x,   qn_w,  qn_b,  xq, D_DIM);
    layernorm_kernel<<<M_TOK, 256>>>(ctx, kvn_w, kvn_b, kv, C_DIM);

    // 2) Q = xq @ wq + bq
    {
        dim3 g(D_DIM / 128, N_TOK / 128, 1);
        mma_gemm<128,128,32,2,4,false,true,false,false><<<g, 256>>>(
            xq, wq, bq, nullptr, q, D_DIM,
            D_DIM, D_DIM, D_DIM, 0, 0, 0, 1.0f);
    }
    // 3) K = kv @ wk + bk
    {
        dim3 g(D_DIM / 128, M_TOK / 128, 1);
        mma_gemm<128,128,32,2,4,false,true,false,false><<<g, 256>>>(
            kv, wk, bk, nullptr, k, C_DIM,
            C_DIM, D_DIM, D_DIM, 0, 0, 0, 1.0f);
    }
    // 4) V = kv @ wv + bv
    {
        dim3 g(D_DIM / 128, M_TOK / 128, 1);
        mma_gemm<128,128,32,2,4,false,true,false,false><<<g, 256>>>(
            kv, wv, bv, nullptr, v, C_DIM,
            C_DIM, D_DIM, D_DIM, 0, 0, 0, 1.0f);
    }
    // 5) S[h] = (Q_h @ K_h^T) / 8     batched over heads, TRANSB
    {
        dim3 g(M_TOK / 128, N_TOK / 128, H_HEADS);
        mma_gemm<128,128,32,2,4,true,false,false,false><<<g, 256>>>(
            q, k, nullptr, nullptr, s, HD_DIM,
            D_DIM, D_DIM, M_TOK,
            HD_DIM, HD_DIM, (long)N_TOK * M_TOK, inv_scale);
    }
    // 6) softmax rows
    softmax_kernel<<<H_HEADS * N_TOK, 256, M_TOK * sizeof(float)>>>(s, M_TOK);

    // 7) O_h = P_h @ V_h              batched, BN=64
    {
        dim3 g(1, N_TOK / 128, H_HEADS);
        mma_gemm<128,64,32,4,2,false,false,false,false><<<g, 256>>>(
            s, v, nullptr, nullptr, o, M_TOK,
            M_TOK, D_DIM, D_DIM,
            (long)N_TOK * M_TOK, HD_DIM, HD_DIM, 1.0f);
    }
    // 8) x1 = o @ wo + bo + x
    {
        dim3 g(D_DIM / 128, N_TOK / 128, 1);
        mma_gemm<128,128,32,2,4,false,true,false,true><<<g, 256>>>(
            o, wo, bo, x, x1, D_DIM,
            D_DIM, D_DIM, D_DIM, 0, 0, 0, 1.0f);
    }
    // 9) hl = LN(x1)
    layernorm_kernel<<<N_TOK, 256>>>(x1, pn_w, pn_b, hl, D_DIM);

    // 10) h1 = gelu(hl @ w1 + b1)
    {
        dim3 g(FF_DIM / 128, N_TOK / 128, 1);
        mma_gemm<128,128,32,2,4,false,true,true,false><<<g, 256>>>(
            hl, w1, b1, nullptr, h1, D_DIM,
            D_DIM, FF_DIM, FF_DIM, 0, 0, 0, 1.0f);
    }
    // 11) out = h1 @ w2 + b2 + x1
    {
        dim3 g(D_DIM / 128, N_TOK / 128, 1);
        mma_gemm<128,128,32,2,4,false,true,false,true><<<g, 256>>>(
            h1, w2, b2, x1, out, FF_DIM,
            FF_DIM, D_DIM, D_DIM, 0, 0, 0, 1.0f);
    }
}

// round 9
// speedup vs baseline: 3.6913x; 1.5662x over previous
#include <cuda_runtime.h>
#include <cuda_bf16.h>
#include <math.h>
#include <stdint.h>

// Problem constants
#define N_TOK 2048
#define M_TOK 2048
#define D_DIM 1024
#define C_DIM 768
#define H_HEADS 16
#define HD_DIM 64
#define FF_DIM 4096

// ---------------------------------------------------------------------------
// Scratch (static device globals)
// ---------------------------------------------------------------------------
__device__ float g_xq[N_TOK * D_DIM];
__device__ float g_kv[M_TOK * C_DIM];
__device__ float g_q [N_TOK * D_DIM];
__device__ float g_k [M_TOK * D_DIM];
__device__ float g_v [M_TOK * D_DIM];
__device__ float g_o [N_TOK * D_DIM];
__device__ float g_x1[N_TOK * D_DIM];
__device__ float g_hl[N_TOK * D_DIM];
__device__ float g_h1[N_TOK * FF_DIM];

// ---------------------------------------------------------------------------
// Helpers
// ---------------------------------------------------------------------------
__device__ __forceinline__ float gelu_tanh(float x) {
    const float k0 = 0.7978845608028654f;
    float x3 = x * x * x;
    return 0.5f * x * (1.0f + tanhf(k0 * (x + 0.044715f * x3)));
}

__device__ __forceinline__ float to_tf32(float x) {
    uint32_t t;
    asm("cvt.rna.tf32.f32 %0, %1;" : "=r"(t) : "f"(x));
    return __uint_as_float(t);
}

__device__ __forceinline__ uint32_t to_tf32_u(float x) {
    uint32_t t;
    asm("cvt.rna.tf32.f32 %0, %1;" : "=r"(t) : "f"(x));
    return t;
}

__device__ __forceinline__ void mma_tf32(float c[4], const uint32_t a[4],
                                         const uint32_t b[2]) {
    asm volatile(
        "mma.sync.aligned.m16n8k8.row.col.f32.tf32.tf32.f32 "
        "{%0,%1,%2,%3}, {%4,%5,%6,%7}, {%8,%9}, {%0,%1,%2,%3};"
        : "+f"(c[0]), "+f"(c[1]), "+f"(c[2]), "+f"(c[3])
        : "r"(a[0]), "r"(a[1]), "r"(a[2]), "r"(a[3]), "r"(b[0]), "r"(b[1]));
}

__device__ __forceinline__ void cp16(float* smem_dst, const float* gsrc) {
    uint32_t s = (uint32_t)__cvta_generic_to_shared(smem_dst);
    asm volatile("cp.async.cg.shared.global [%0], [%1], 16;" :: "r"(s), "l"(gsrc));
}
#define CP_COMMIT() asm volatile("cp.async.commit_group;")
#define CP_WAIT0()  asm volatile("cp.async.wait_group 0;")

// reduce across the 4 lanes of a quad group (tig dimension)
__device__ __forceinline__ float qreduce_max(float v) {
    v = fmaxf(v, __shfl_xor_sync(0xffffffffu, v, 1));
    v = fmaxf(v, __shfl_xor_sync(0xffffffffu, v, 2));
    return v;
}
__device__ __forceinline__ float qreduce_sum(float v) {
    v += __shfl_xor_sync(0xffffffffu, v, 1);
    v += __shfl_xor_sync(0xffffffffu, v, 2);
    return v;
}

__device__ __forceinline__ float blockReduceSum(float v) {
    __shared__ float s[32];
    __syncthreads();
    int lane = threadIdx.x & 31, wid = threadIdx.x >> 5;
    #pragma unroll
    for (int o = 16; o > 0; o >>= 1) v += __shfl_down_sync(0xffffffffu, v, o);
    if (lane == 0) s[wid] = v;
    __syncthreads();
    int nw = (blockDim.x + 31) >> 5;
    v = (threadIdx.x < nw) ? s[threadIdx.x] : 0.0f;
    if (wid == 0) {
        #pragma unroll
        for (int o = 16; o > 0; o >>= 1) v += __shfl_down_sync(0xffffffffu, v, o);
        if (lane == 0) s[0] = v;
    }
    __syncthreads();
    return s[0];
}

// ---------------------------------------------------------------------------
// LayerNorm: one block per row
// ---------------------------------------------------------------------------
__global__ void layernorm_kernel(const float* __restrict__ in,
                                 const float* __restrict__ w,
                                 const float* __restrict__ b,
                                 float* __restrict__ out, int cols)
{
    long row = blockIdx.x;
    const float* x = in + row * cols;
    float sum = 0.0f, sumsq = 0.0f;
    for (int i = threadIdx.x; i < cols; i += blockDim.x) {
        float v = x[i];
        sum += v;
        sumsq += v * v;
    }
    float tsum = blockReduceSum(sum);
    float tsq  = blockReduceSum(sumsq);
    float mean = tsum / cols;
    float var  = tsq / cols - mean * mean;
    float rstd = rsqrtf(var + 1e-12f);
    float* o = out + row * cols;
    for (int i = threadIdx.x; i < cols; i += blockDim.x) {
        o[i] = (x[i] - mean) * rstd * w[i] + b[i];
    }
}

// ---------------------------------------------------------------------------
// tf32 tensor-core GEMM with 2-stage cp.async pipeline (dynamic smem).
// C[M,N] = alpha*A[M,K] @ B[K,N] (+bias)(gelu)(+res)
// ---------------------------------------------------------------------------
template<int BM, int BN, int BK, int WARPS_M, int WARPS_N,
         bool BIAS, bool GELU, bool RES>
__global__ __launch_bounds__(256)
void mma_gemm(const float* __restrict__ A, const float* __restrict__ B,
              const float* __restrict__ bias, const float* __restrict__ res,
              float* __restrict__ C,
              int Kdim, int lda, int ldb, int ldc, float alpha)
{
    extern __shared__ float smem[];
    constexpr int ASTR = BK + 4;
    constexpr int BS_C = BN + 8;
    constexpr int AOFF = 2 * BM * ASTR;

    constexpr int WM = BM / WARPS_M;
    constexpr int WN = BN / WARPS_N;
    constexpr int MT = WM / 16;
    constexpr int NT = WN / 8;

    const int m0 = blockIdx.y * BM;
    const int n0 = blockIdx.x * BN;

    const int tid  = threadIdx.x;
    const int warp = tid >> 5;
    const int lane = tid & 31;
    const int grp  = lane >> 2;
    const int tig  = lane & 3;
    const int wm0  = (warp / WARPS_N) * WM;
    const int wn0  = (warp % WARPS_N) * WN;

    float acc[MT][NT][4];
    #pragma unroll
    for (int i = 0; i < MT; i++)
        #pragma unroll
        for (int j = 0; j < NT; j++)
            #pragma unroll
            for (int r = 0; r < 4; r++) acc[i][j][r] = 0.0f;

    constexpr int A_V4 = BM * BK / 4;
    constexpr int B_V4 = BK * BN / 4;

    auto fill = [&](int buf, int k0) {
        float* Ab = smem + buf * BM * ASTR;
        #pragma unroll
        for (int it = 0; it < A_V4 / 256; it++) {
            int i  = tid + it * 256;
            int m  = i / (BK / 4);
            int kq = (i % (BK / 4)) * 4;
            cp16(&Ab[m * ASTR + kq], &A[(long)(m0 + m) * lda + k0 + kq]);
        }
        float* Bb = smem + AOFF + buf * BK * BS_C;
        #pragma unroll
        for (int it = 0; it < B_V4 / 256; it++) {
            int i  = tid + it * 256;
            int kk = i / (BN / 4);
            int n  = (i % (BN / 4)) * 4;
            cp16(&Bb[kk * BS_C + n], &B[(long)(k0 + kk) * ldb + n0 + n]);
        }
    };

    const int nt = Kdim / BK;
    fill(0, 0);
    CP_COMMIT();

    for (int t = 0; t < nt; t++) {
        CP_WAIT0();
        __syncthreads();
        if (t + 1 < nt) {
            fill((t + 1) & 1, (t + 1) * BK);
            CP_COMMIT();
        }
        const float* Ab = smem + (t & 1) * BM * ASTR;
        const float* Bb = smem + AOFF + (t & 1) * BK * BS_C;

        #pragma unroll
        for (int ks = 0; ks < BK / 8; ks++) {
            const int kb = ks * 8;
            uint32_t af[MT][4];
            #pragma unroll
            for (int mi = 0; mi < MT; mi++) {
                int r = wm0 + mi * 16 + grp;
                af[mi][0] = to_tf32_u(Ab[(r    ) * ASTR + kb + tig    ]);
                af[mi][1] = to_tf32_u(Ab[(r + 8) * ASTR + kb + tig    ]);
                af[mi][2] = to_tf32_u(Ab[(r    ) * ASTR + kb + tig + 4]);
                af[mi][3] = to_tf32_u(Ab[(r + 8) * ASTR + kb + tig + 4]);
            }
            uint32_t bf[NT][2];
            #pragma unroll
            for (int ni = 0; ni < NT; ni++) {
                int c = wn0 + ni * 8 + grp;
                bf[ni][0] = to_tf32_u(Bb[(kb + tig    ) * BS_C + c]);
                bf[ni][1] = to_tf32_u(Bb[(kb + tig + 4) * BS_C + c]);
            }
            #pragma unroll
            for (int mi = 0; mi < MT; mi++)
                #pragma unroll
                for (int ni = 0; ni < NT; ni++)
                    mma_tf32(acc[mi][ni], af[mi], bf[ni]);
        }
        __syncthreads();
    }

    // epilogue
    #pragma unroll
    for (int mi = 0; mi < MT; mi++) {
        #pragma unroll
        for (int ni = 0; ni < NT; ni++) {
            long r0 = m0 + wm0 + mi * 16 + grp;
            long r1 = r0 + 8;
            int  c0 = n0 + wn0 + ni * 8 + tig * 2;
            float v0 = acc[mi][ni][0] * alpha;
            float v1 = acc[mi][ni][1] * alpha;
            float v2 = acc[mi][ni][2] * alpha;
            float v3 = acc[mi][ni][3] * alpha;
            if (BIAS) {
                float bb0 = bias[c0], bb1 = bias[c0 + 1];
                v0 += bb0; v1 += bb1; v2 += bb0; v3 += bb1;
            }
            if (GELU) {
                v0 = gelu_tanh(v0); v1 = gelu_tanh(v1);
                v2 = gelu_tanh(v2); v3 = gelu_tanh(v3);
            }
            if (RES) {
                const float2 r0v = *reinterpret_cast<const float2*>(&res[r0 * ldc + c0]);
                const float2 r1v = *reinterpret_cast<const float2*>(&res[r1 * ldc + c0]);
                v0 += r0v.x; v1 += r0v.y; v2 += r1v.x; v3 += r1v.y;
            }
            *reinterpret_cast<float2*>(&C[r0 * ldc + c0]) = make_float2(v0, v1);
            *reinterpret_cast<float2*>(&C[r1 * ldc + c0]) = make_float2(v2, v3);
        }
    }
}

// ---------------------------------------------------------------------------
// Flash attention (tf32 MMA, online softmax).
// One block = one head x 128 q rows. 8 warps; warp w owns q rows [16w,16w+16)
// and ALL 64 kv columns -> softmax row state is warp-private (full row lives
// in one quad group; qreduce over tig is a complete row reduction).
// smem: Qs[128][68] | Ks[64][68] | Vs[64][72] | Ps[128][68]  = 105472 B
// ---------------------------------------------------------------------------
#define FA_BQ  128
#define FA_BKV 64
#define QS_STR 68
#define KS_STR 68
#define VS_STR 72
#define PS_STR 68

__global__ __launch_bounds__(256, 2)
void flash_attn(const float* __restrict__ q, const float* __restrict__ k,
                const float* __restrict__ v, float* __restrict__ o)
{
    extern __shared__ float smem[];
    float* sQ = smem;                         // 128*68
    float* sK = sQ + FA_BQ * QS_STR;          // 64*68
    float* sV = sK + FA_BKV * KS_STR;         // 64*72
    float* sP = sV + FA_BKV * VS_STR;         // 128*68

    const int h  = blockIdx.y;
    const int q0 = blockIdx.x * FA_BQ;
    const float* qh = q + (size_t)q0 * D_DIM + h * HD_DIM;
    const float* kh = k + h * HD_DIM;
    const float* vh = v + h * HD_DIM;

    const int tid  = threadIdx.x;
    const int warp = tid >> 5;
    const int lane = tid & 31;
    const int grp  = lane >> 2;
    const int tig  = lane & 3;
    const int wm0  = warp * 16;               // 8 warp-rows of 16

    // load Q (scaled by 1/8, tf32)
    #pragma unroll
    for (int it = 0; it < 8; it++) {
        int i  = tid + it * 256;
        int m  = i >> 4;
        int kq = (i & 15) * 4;
        float4 qv = *reinterpret_cast<const float4*>(&qh[(size_t)m * D_DIM + kq]);
        sQ[m * QS_STR + kq + 0] = to_tf32(qv.x * 0.125f);
        sQ[m * QS_STR + kq + 1] = to_tf32(qv.y * 0.125f);
        sQ[m * QS_STR + kq + 2] = to_tf32(qv.z * 0.125f);
        sQ[m * QS_STR + kq + 3] = to_tf32(qv.w * 0.125f);
    }

    float m_i[2] = {-1e30f, -1e30f};
    float l_i[2] = {0.0f, 0.0f};
    float oacc[8][4];
    #pragma unroll
    for (int ni = 0; ni < 8; ni++)
        #pragma unroll
        for (int r = 0; r < 4; r++) oacc[ni][r] = 0.0f;

    for (int t0 = 0; t0 < M_TOK; t0 += FA_BKV) {
        // fill K and V tiles (64 rows x 64 cols each)
        #pragma unroll
        for (int it = 0; it < 4; it++) {
            int i  = tid + it * 256;
            int r  = i >> 4;
            int kq = (i & 15) * 4;
            float4 kv4 = *reinterpret_cast<const float4*>(
                &kh[(size_t)(t0 + r) * D_DIM + kq]);
            sK[r * KS_STR + kq + 0] = to_tf32(kv4.x);
            sK[r * KS_STR + kq + 1] = to_tf32(kv4.y);
            sK[r * KS_STR + kq + 2] = to_tf32(kv4.z);
            sK[r * KS_STR + kq + 3] = to_tf32(kv4.w);
            float4 vv4 = *reinterpret_cast<const float4*>(
                &vh[(size_t)(t0 + r) * D_DIM + kq]);
            sV[r * VS_STR + kq + 0] = to_tf32(vv4.x);
            sV[r * VS_STR + kq + 1] = to_tf32(vv4.y);
            sV[r * VS_STR + kq + 2] = to_tf32(vv4.z);
            sV[r * VS_STR + kq + 3] = to_tf32(vv4.w);
        }
        __syncthreads();

        // S = Qs @ Ks^T  (warp tile: 16 x 64, K=64)
        float sacc[8][4];
        #pragma unroll
        for (int ni = 0; ni < 8; ni++)
            #pragma unroll
            for (int r = 0; r < 4; r++) sacc[ni][r] = 0.0f;

        #pragma unroll
        for (int ks = 0; ks < 8; ks++) {
            const int kb = ks * 8;
            uint32_t af[4];
            af[0] = __float_as_uint(sQ[(wm0 + grp    ) * QS_STR + kb + tig    ]);
            af[1] = __float_as_uint(sQ[(wm0 + grp + 8) * QS_STR + kb + tig    ]);
            af[2] = __float_as_uint(sQ[(wm0 + grp    ) * QS_STR + kb + tig + 4]);
            af[3] = __float_as_uint(sQ[(wm0 + grp + 8) * QS_STR + kb + tig + 4]);
            #pragma unroll
            for (int ni = 0; ni < 8; ni++) {
                uint32_t bf[2];
                int c = ni * 8 + grp;
                bf[0] = __float_as_uint(sK[c * KS_STR + kb + tig    ]);
                bf[1] = __float_as_uint(sK[c * KS_STR + kb + tig + 4]);
                mma_tf32(sacc[ni], af, bf);
            }
        }

        // online softmax: rows are warp-private, qreduce = full row reduction
        #pragma unroll
        for (int half = 0; half < 2; half++) {
            float mx = -1e30f;
            #pragma unroll
            for (int ni = 0; ni < 8; ni++)
                mx = fmaxf(mx, fmaxf(sacc[ni][2*half], sacc[ni][2*half+1]));
            mx = qreduce_max(mx);
            float mold = m_i[half];
            float mnew = fmaxf(mold, mx);
            float scale = __expf(mold - mnew);
            m_i[half] = mnew;

            int row = wm0 + grp + half * 8;
            float rsum = 0.0f;
            #pragma unroll
            for (int ni = 0; ni < 8; ni++) {
                float p0 = __expf(sacc[ni][2*half    ] - mnew);
                float p1 = __expf(sacc[ni][2*half + 1] - mnew);
                rsum += p0 + p1;
                *reinterpret_cast<float2*>(&sP[row * PS_STR + ni * 8 + 2 * tig]) =
                    make_float2(to_tf32(p0), to_tf32(p1));
            }
            rsum = qreduce_sum(rsum);
            l_i[half] = l_i[half] * scale + rsum;
            #pragma unroll
            for (int ni = 0; ni < 8; ni++) {
                oacc[ni][2*half    ] *= scale;
                oacc[ni][2*half + 1] *= scale;
            }
        }
        __syncwarp();   // P writes -> P reads are cross-lane within this warp only

        // O += Ps @ Vs  (warp tile: 16 x 64, K=64; A rows are warp-own sP rows)
        #pragma unroll
        for (int ks = 0; ks < 8; ks++) {
            const int kb = ks * 8;
            uint32_t af[4];
            af[0] = __float_as_uint(sP[(wm0 + grp    ) * PS_STR + kb + tig    ]);
            af[1] = __float_as_uint(sP[(wm0 + grp + 8) * PS_STR + kb + tig    ]);
            af[2] = __float_as_uint(sP[(wm0 + grp    ) * PS_STR + kb + tig + 4]);
            af[3] = __float_as_uint(sP[(wm0 + grp + 8) * PS_STR + kb + tig + 4]);
            #pragma unroll
            for (int ni = 0; ni < 8; ni++) {
                uint32_t bf[2];
                int c = ni * 8 + grp;
                bf[0] = __float_as_uint(sV[(kb + tig    ) * VS_STR + c]);
                bf[1] = __float_as_uint(sV[(kb + tig + 4) * VS_STR + c]);
                mma_tf32(oacc[ni], af, bf);
            }
        }
        __syncthreads();   // before next tile overwrites sK/sV
    }

    // epilogue: O /= l, write to o at head column block
    float inv0 = 1.0f / l_i[0];
    float inv1 = 1.0f / l_i[1];
    long r0 = q0 + wm0 + grp;
    long r1 = r0 + 8;
    #pragma unroll
    for (int ni = 0; ni < 8; ni++) {
        int c0 = h * HD_DIM + ni * 8 + 2 * tig;
        *reinterpret_cast<float2*>(&o[r0 * D_DIM + c0]) =
            make_float2(oacc[ni][0] * inv0, oacc[ni][1] * inv0);
        *reinterpret_cast<float2*>(&o[r1 * D_DIM + c0]) =
            make_float2(oacc[ni][2] * inv1, oacc[ni][3] * inv1);
    }
}

// ---------------------------------------------------------------------------
// Launch
// ---------------------------------------------------------------------------
#define GEMM_SMEM ((2 * 128 * 36 + 2 * 32 * 136) * 4)          // 71680
#define FA_SMEM   ((FA_BQ * QS_STR + FA_BKV * KS_STR + FA_BKV * VS_STR + FA_BQ * PS_STR) * 4)

extern "C" void kernel_launch(void* const* d_in, const int* in_sizes, int n_in,
                              void* d_out, int out_size)
{
    const float* x    = (const float*)d_in[0];
    const float* ctx  = (const float*)d_in[1];
    const float* wq   = (const float*)d_in[2];
    const float* bq   = (const float*)d_in[3];
    const float* wk   = (const float*)d_in[4];
    const float* bk   = (const float*)d_in[5];
    const float* wv   = (const float*)d_in[6];
    const float* bv   = (const float*)d_in[7];
    const float* wo   = (const float*)d_in[8];
    const float* bo   = (const float*)d_in[9];
    const float* w1   = (const float*)d_in[10];
    const float* b1   = (const float*)d_in[11];
    const float* w2   = (const float*)d_in[12];
    const float* b2   = (const float*)d_in[13];
    const float* qn_w = (const float*)d_in[14];
    const float* qn_b = (const float*)d_in[15];
    const float* kvn_w= (const float*)d_in[16];
    const float* kvn_b= (const float*)d_in[17];
    const float* pn_w = (const float*)d_in[18];
    const float* pn_b = (const float*)d_in[19];
    float* out = (float*)d_out;

    float *xq, *kv, *q, *k, *v, *o, *x1, *hl, *h1;
    cudaGetSymbolAddress((void**)&xq, g_xq);
    cudaGetSymbolAddress((void**)&kv, g_kv);
    cudaGetSymbolAddress((void**)&q,  g_q);
    cudaGetSymbolAddress((void**)&k,  g_k);
    cudaGetSymbolAddress((void**)&v,  g_v);
    cudaGetSymbolAddress((void**)&o,  g_o);
    cudaGetSymbolAddress((void**)&x1, g_x1);
    cudaGetSymbolAddress((void**)&hl, g_hl);
    cudaGetSymbolAddress((void**)&h1, g_h1);

    auto kProj = mma_gemm<128,128,32,2,4,true,false,false>;
    auto kRes  = mma_gemm<128,128,32,2,4,true,false,true>;
    auto kGelu = mma_gemm<128,128,32,2,4,true,true,false>;
    cudaFuncSetAttribute(kProj, cudaFuncAttributeMaxDynamicSharedMemorySize, GEMM_SMEM);
    cudaFuncSetAttribute(kRes,  cudaFuncAttributeMaxDynamicSharedMemorySize, GEMM_SMEM);
    cudaFuncSetAttribute(kGelu, cudaFuncAttributeMaxDynamicSharedMemorySize, GEMM_SMEM);
    cudaFuncSetAttribute(flash_attn, cudaFuncAttributeMaxDynamicSharedMemorySize, FA_SMEM);

    // 1) pre-norms
    layernorm_kernel<<<N_TOK, 256>>>(x,   qn_w,  qn_b,  xq, D_DIM);
    layernorm_kernel<<<M_TOK, 256>>>(ctx, kvn_w, kvn_b, kv, C_DIM);

    // 2) Q/K/V projections
    {
        dim3 g(D_DIM / 128, N_TOK / 128, 1);
        kProj<<<g, 256, GEMM_SMEM>>>(xq, wq, bq, nullptr, q, D_DIM,
                                     D_DIM, D_DIM, D_DIM, 1.0f);
    }
    {
        dim3 g(D_DIM / 128, M_TOK / 128, 1);
        kProj<<<g, 256, GEMM_SMEM>>>(kv, wk, bk, nullptr, k, C_DIM,
                                     C_DIM, D_DIM, D_DIM, 1.0f);
        kProj<<<g, 256, GEMM_SMEM>>>(kv, wv, bv, nullptr, v, C_DIM,
                                     C_DIM, D_DIM, D_DIM, 1.0f);
    }

    // 3) fused attention: o = softmax(QK^T/8) V   (per head)
    {
        dim3 g(N_TOK / FA_BQ, H_HEADS, 1);
        flash_attn<<<g, 256, FA_SMEM>>>(q, k, v, o);
    }

    // 4) x1 = o @ wo + bo + x
    {
        dim3 g(D_DIM / 128, N_TOK / 128, 1);
        kRes<<<g, 256, GEMM_SMEM>>>(o, wo, bo, x, x1, D_DIM,
                                    D_DIM, D_DIM, D_DIM, 1.0f);
    }
    // 5) hl = LN(x1)
    layernorm_kernel<<<N_TOK, 256>>>(x1, pn_w, pn_b, hl, D_DIM);

    // 6) h1 = gelu(hl @ w1 + b1)
    {
        dim3 g(FF_DIM / 128, N_TOK / 128, 1);
        kGelu<<<g, 256, GEMM_SMEM>>>(hl, w1, b1, nullptr, h1, D_DIM,
                                     D_DIM, FF_DIM, FF_DIM, 1.0f);
    }
    // 7) out = h1 @ w2 + b2 + x1
    {
        dim3 g(D_DIM / 128, N_TOK / 128, 1);
        kRes<<<g, 256, GEMM_SMEM>>>(h1, w2, b2, x1, out, FF_DIM,
                                    FF_DIM, D_DIM, D_DIM, 1.0f);
    }
}

// round 14
// speedup vs baseline: 3.7679x; 1.0207x over previous
#include <cuda_runtime.h>
#include <cuda_bf16.h>
#include <math.h>
#include <stdint.h>

// Problem constants
#define N_TOK 2048
#define M_TOK 2048
#define D_DIM 1024
#define C_DIM 768
#define H_HEADS 16
#define HD_DIM 64
#define FF_DIM 4096

// ---------------------------------------------------------------------------
// Scratch (static device globals)
// ---------------------------------------------------------------------------
__device__ float g_xq[N_TOK * D_DIM];
__device__ float g_kv[M_TOK * C_DIM];
__device__ float g_q [N_TOK * D_DIM];
__device__ float g_k [M_TOK * D_DIM];
__device__ float g_v [M_TOK * D_DIM];
__device__ float g_o [N_TOK * D_DIM];
__device__ float g_x1[N_TOK * D_DIM];
__device__ float g_hl[N_TOK * D_DIM];
__device__ float g_h1[N_TOK * FF_DIM];
// tf32-pre-rounded weights
__device__ float g_wq[D_DIM * D_DIM];
__device__ float g_wk[C_DIM * D_DIM];
__device__ float g_wv[C_DIM * D_DIM];
__device__ float g_wo[D_DIM * D_DIM];
__device__ float g_w1[D_DIM * FF_DIM];
__device__ float g_w2[FF_DIM * D_DIM];

// ---------------------------------------------------------------------------
// Helpers
// ---------------------------------------------------------------------------
__device__ __forceinline__ float gelu_tanh(float x) {
    const float k0 = 0.7978845608028654f;
    float x3 = x * x * x;
    return 0.5f * x * (1.0f + tanhf(k0 * (x + 0.044715f * x3)));
}

__device__ __forceinline__ float to_tf32(float x) {
    uint32_t t;
    asm("cvt.rna.tf32.f32 %0, %1;" : "=r"(t) : "f"(x));
    return __uint_as_float(t);
}

__device__ __forceinline__ void mma_tf32(float c[4], const uint32_t a[4],
                                         const uint32_t b[2]) {
    asm volatile(
        "mma.sync.aligned.m16n8k8.row.col.f32.tf32.tf32.f32 "
        "{%0,%1,%2,%3}, {%4,%5,%6,%7}, {%8,%9}, {%0,%1,%2,%3};"
        : "+f"(c[0]), "+f"(c[1]), "+f"(c[2]), "+f"(c[3])
        : "r"(a[0]), "r"(a[1]), "r"(a[2]), "r"(a[3]), "r"(b[0]), "r"(b[1]));
}

__device__ __forceinline__ void cp16(float* smem_dst, const float* gsrc) {
    uint32_t s = (uint32_t)__cvta_generic_to_shared(smem_dst);
    asm volatile("cp.async.cg.shared.global [%0], [%1], 16;" :: "r"(s), "l"(gsrc));
}
#define CP_COMMIT() asm volatile("cp.async.commit_group;")
#define CP_WAIT0()  asm volatile("cp.async.wait_group 0;")

// reduce across the 4 lanes of a quad group (tig dimension)
__device__ __forceinline__ float qreduce_max(float v) {
    v = fmaxf(v, __shfl_xor_sync(0xffffffffu, v, 1));
    v = fmaxf(v, __shfl_xor_sync(0xffffffffu, v, 2));
    return v;
}
__device__ __forceinline__ float qreduce_sum(float v) {
    v += __shfl_xor_sync(0xffffffffu, v, 1);
    v += __shfl_xor_sync(0xffffffffu, v, 2);
    return v;
}

__device__ __forceinline__ float blockReduceSum(float v) {
    __shared__ float s[32];
    __syncthreads();
    int lane = threadIdx.x & 31, wid = threadIdx.x >> 5;
    #pragma unroll
    for (int o = 16; o > 0; o >>= 1) v += __shfl_down_sync(0xffffffffu, v, o);
    if (lane == 0) s[wid] = v;
    __syncthreads();
    int nw = (blockDim.x + 31) >> 5;
    v = (threadIdx.x < nw) ? s[threadIdx.x] : 0.0f;
    if (wid == 0) {
        #pragma unroll
        for (int o = 16; o > 0; o >>= 1) v += __shfl_down_sync(0xffffffffu, v, o);
        if (lane == 0) s[0] = v;
    }
    __syncthreads();
    return s[0];
}

// ---------------------------------------------------------------------------
// tf32 pre-round (elementwise, float4 grid-stride)
// ---------------------------------------------------------------------------
__global__ void round_tf32_kernel(const float* __restrict__ in,
                                  float* __restrict__ out, int n4)
{
    for (int i = blockIdx.x * blockDim.x + threadIdx.x; i < n4;
         i += gridDim.x * blockDim.x) {
        float4 v = reinterpret_cast<const float4*>(in)[i];
        v.x = to_tf32(v.x); v.y = to_tf32(v.y);
        v.z = to_tf32(v.z); v.w = to_tf32(v.w);
        reinterpret_cast<float4*>(out)[i] = v;
    }
}

// ---------------------------------------------------------------------------
// LayerNorm: one block per row; output rounded to tf32 (feeds GEMM A-side)
// ---------------------------------------------------------------------------
__global__ void layernorm_kernel(const float* __restrict__ in,
                                 const float* __restrict__ w,
                                 const float* __restrict__ b,
                                 float* __restrict__ out, int cols)
{
    long row = blockIdx.x;
    const float* x = in + row * cols;
    float sum = 0.0f, sumsq = 0.0f;
    for (int i = threadIdx.x; i < cols; i += blockDim.x) {
        float v = x[i];
        sum += v;
        sumsq += v * v;
    }
    float tsum = blockReduceSum(sum);
    float tsq  = blockReduceSum(sumsq);
    float mean = tsum / cols;
    float var  = tsq / cols - mean * mean;
    float rstd = rsqrtf(var + 1e-12f);
    float* o = out + row * cols;
    for (int i = threadIdx.x; i < cols; i += blockDim.x) {
        o[i] = to_tf32((x[i] - mean) * rstd * w[i] + b[i]);
    }
}

// ---------------------------------------------------------------------------
// tf32 tensor-core GEMM, 2-stage cp.async pipeline, NO cvt in inner loop:
// all operands are pre-rounded to tf32 in gmem, so HW truncation is exact.
// C[M,N] = A[M,K] @ B[K,N] (+bias)(gelu)(+res); optional tf32-round of output.
// ---------------------------------------------------------------------------
template<int BM, int BN, int BK, int WARPS_M, int WARPS_N,
         bool BIAS, bool GELU, bool RES, bool ROUND>
__global__ __launch_bounds__(256, 2)
void mma_gemm(const float* __restrict__ A, const float* __restrict__ B,
              const float* __restrict__ bias, const float* __restrict__ res,
              float* __restrict__ C,
              int Kdim, int lda, int ldb, int ldc)
{
    extern __shared__ float smem[];
    constexpr int ASTR = BK + 4;
    constexpr int BS_C = BN + 8;
    constexpr int AOFF = 2 * BM * ASTR;

    constexpr int WM = BM / WARPS_M;
    constexpr int WN = BN / WARPS_N;
    constexpr int MT = WM / 16;
    constexpr int NT = WN / 8;

    const int m0 = blockIdx.y * BM;
    const int n0 = blockIdx.x * BN;

    const int tid  = threadIdx.x;
    const int warp = tid >> 5;
    const int lane = tid & 31;
    const int grp  = lane >> 2;
    const int tig  = lane & 3;
    const int wm0  = (warp / WARPS_N) * WM;
    const int wn0  = (warp % WARPS_N) * WN;

    float acc[MT][NT][4];
    #pragma unroll
    for (int i = 0; i < MT; i++)
        #pragma unroll
        for (int j = 0; j < NT; j++)
            #pragma unroll
            for (int r = 0; r < 4; r++) acc[i][j][r] = 0.0f;

    constexpr int A_V4 = BM * BK / 4;
    constexpr int B_V4 = BK * BN / 4;

    auto fill = [&](int buf, int k0) {
        float* Ab = smem + buf * BM * ASTR;
        #pragma unroll
        for (int it = 0; it < A_V4 / 256; it++) {
            int i  = tid + it * 256;
            int m  = i / (BK / 4);
            int kq = (i % (BK / 4)) * 4;
            cp16(&Ab[m * ASTR + kq], &A[(long)(m0 + m) * lda + k0 + kq]);
        }
        float* Bb = smem + AOFF + buf * BK * BS_C;
        #pragma unroll
        for (int it = 0; it < B_V4 / 256; it++) {
            int i  = tid + it * 256;
            int kk = i / (BN / 4);
            int n  = (i % (BN / 4)) * 4;
            cp16(&Bb[kk * BS_C + n], &B[(long)(k0 + kk) * ldb + n0 + n]);
        }
    };

    const int nt = Kdim / BK;
    fill(0, 0);
    CP_COMMIT();

    for (int t = 0; t < nt; t++) {
        CP_WAIT0();
        __syncthreads();
        if (t + 1 < nt) {
            fill((t + 1) & 1, (t + 1) * BK);
            CP_COMMIT();
        }
        const float* Ab = smem + (t & 1) * BM * ASTR;
        const float* Bb = smem + AOFF + (t & 1) * BK * BS_C;

        #pragma unroll
        for (int ks = 0; ks < BK / 8; ks++) {
            const int kb = ks * 8;
            uint32_t af[MT][4];
            #pragma unroll
            for (int mi = 0; mi < MT; mi++) {
                int r = wm0 + mi * 16 + grp;
                af[mi][0] = __float_as_uint(Ab[(r    ) * ASTR + kb + tig    ]);
                af[mi][1] = __float_as_uint(Ab[(r + 8) * ASTR + kb + tig    ]);
                af[mi][2] = __float_as_uint(Ab[(r    ) * ASTR + kb + tig + 4]);
                af[mi][3] = __float_as_uint(Ab[(r + 8) * ASTR + kb + tig + 4]);
            }
            uint32_t bf[NT][2];
            #pragma unroll
            for (int ni = 0; ni < NT; ni++) {
                int c = wn0 + ni * 8 + grp;
                bf[ni][0] = __float_as_uint(Bb[(kb + tig    ) * BS_C + c]);
                bf[ni][1] = __float_as_uint(Bb[(kb + tig + 4) * BS_C + c]);
            }
            #pragma unroll
            for (int mi = 0; mi < MT; mi++)
                #pragma unroll
                for (int ni = 0; ni < NT; ni++)
                    mma_tf32(acc[mi][ni], af[mi], bf[ni]);
        }
        __syncthreads();
    }

    // epilogue
    #pragma unroll
    for (int mi = 0; mi < MT; mi++) {
        #pragma unroll
        for (int ni = 0; ni < NT; ni++) {
            long r0 = m0 + wm0 + mi * 16 + grp;
            long r1 = r0 + 8;
            int  c0 = n0 + wn0 + ni * 8 + tig * 2;
            float v0 = acc[mi][ni][0];
            float v1 = acc[mi][ni][1];
            float v2 = acc[mi][ni][2];
            float v3 = acc[mi][ni][3];
            if (BIAS) {
                float bb0 = bias[c0], bb1 = bias[c0 + 1];
                v0 += bb0; v1 += bb1; v2 += bb0; v3 += bb1;
            }
            if (GELU) {
                v0 = gelu_tanh(v0); v1 = gelu_tanh(v1);
                v2 = gelu_tanh(v2); v3 = gelu_tanh(v3);
            }
            if (RES) {
                const float2 r0v = *reinterpret_cast<const float2*>(&res[r0 * ldc + c0]);
                const float2 r1v = *reinterpret_cast<const float2*>(&res[r1 * ldc + c0]);
                v0 += r0v.x; v1 += r0v.y; v2 += r1v.x; v3 += r1v.y;
            }
            if (ROUND) {
                v0 = to_tf32(v0); v1 = to_tf32(v1);
                v2 = to_tf32(v2); v3 = to_tf32(v3);
            }
            *reinterpret_cast<float2*>(&C[r0 * ldc + c0]) = make_float2(v0, v1);
            *reinterpret_cast<float2*>(&C[r1 * ldc + c0]) = make_float2(v2, v3);
        }
    }
}

// ---------------------------------------------------------------------------
// Flash attention (tf32 MMA, online softmax).
// One block = one head x 128 q rows. 8 warps; warp w owns q rows [16w,16w+16)
// and ALL 64 kv columns -> softmax row state is warp-private.
// q/k/v are tf32-pre-rounded in gmem (GEMM epilogue), so fills need no cvt
// (Q scale 0.125 is a power of two -> exact).
// smem: Qs[128][68] | Ks[64][68] | Vs[64][72] | Ps[128][68]  = 105472 B
// ---------------------------------------------------------------------------
#define FA_BQ  128
#define FA_BKV 64
#define QS_STR 68
#define KS_STR 68
#define VS_STR 72
#define PS_STR 68

__global__ __launch_bounds__(256, 2)
void flash_attn(const float* __restrict__ q, const float* __restrict__ k,
                const float* __restrict__ v, float* __restrict__ o)
{
    extern __shared__ float smem[];
    float* sQ = smem;
    float* sK = sQ + FA_BQ * QS_STR;
    float* sV = sK + FA_BKV * KS_STR;
    float* sP = sV + FA_BKV * VS_STR;

    const int h  = blockIdx.y;
    const int q0 = blockIdx.x * FA_BQ;
    const float* qh = q + (size_t)q0 * D_DIM + h * HD_DIM;
    const float* kh = k + h * HD_DIM;
    const float* vh = v + h * HD_DIM;

    const int tid  = threadIdx.x;
    const int warp = tid >> 5;
    const int lane = tid & 31;
    const int grp  = lane >> 2;
    const int tig  = lane & 3;
    const int wm0  = warp * 16;

    // load Q (scaled by 1/8 — exact on tf32 values)
    #pragma unroll
    for (int it = 0; it < 8; it++) {
        int i  = tid + it * 256;
        int m  = i >> 4;
        int kq = (i & 15) * 4;
        float4 qv = *reinterpret_cast<const float4*>(&qh[(size_t)m * D_DIM + kq]);
        sQ[m * QS_STR + kq + 0] = qv.x * 0.125f;
        sQ[m * QS_STR + kq + 1] = qv.y * 0.125f;
        sQ[m * QS_STR + kq + 2] = qv.z * 0.125f;
        sQ[m * QS_STR + kq + 3] = qv.w * 0.125f;
    }

    float m_i[2] = {-1e30f, -1e30f};
    float l_i[2] = {0.0f, 0.0f};
    float oacc[8][4];
    #pragma unroll
    for (int ni = 0; ni < 8; ni++)
        #pragma unroll
        for (int r = 0; r < 4; r++) oacc[ni][r] = 0.0f;

    for (int t0 = 0; t0 < M_TOK; t0 += FA_BKV) {
        #pragma unroll
        for (int it = 0; it < 4; it++) {
            int i  = tid + it * 256;
            int r  = i >> 4;
            int kq = (i & 15) * 4;
            *reinterpret_cast<float4*>(&sK[r * KS_STR + kq]) =
                *reinterpret_cast<const float4*>(&kh[(size_t)(t0 + r) * D_DIM + kq]);
            *reinterpret_cast<float4*>(&sV[r * VS_STR + kq]) =
                *reinterpret_cast<const float4*>(&vh[(size_t)(t0 + r) * D_DIM + kq]);
        }
        __syncthreads();

        // S = Qs @ Ks^T  (warp tile 16 x 64, K=64)
        float sacc[8][4];
        #pragma unroll
        for (int ni = 0; ni < 8; ni++)
            #pragma unroll
            for (int r = 0; r < 4; r++) sacc[ni][r] = 0.0f;

        #pragma unroll
        for (int ks = 0; ks < 8; ks++) {
            const int kb = ks * 8;
            uint32_t af[4];
            af[0] = __float_as_uint(sQ[(wm0 + grp    ) * QS_STR + kb + tig    ]);
            af[1] = __float_as_uint(sQ[(wm0 + grp + 8) * QS_STR + kb + tig    ]);
            af[2] = __float_as_uint(sQ[(wm0 + grp    ) * QS_STR + kb + tig + 4]);
            af[3] = __float_as_uint(sQ[(wm0 + grp + 8) * QS_STR + kb + tig + 4]);
            #pragma unroll
            for (int ni = 0; ni < 8; ni++) {
                uint32_t bf[2];
                int c = ni * 8 + grp;
                bf[0] = __float_as_uint(sK[c * KS_STR + kb + tig    ]);
                bf[1] = __float_as_uint(sK[c * KS_STR + kb + tig + 4]);
                mma_tf32(sacc[ni], af, bf);
            }
        }

        // online softmax (rows warp-private)
        #pragma unroll
        for (int half = 0; half < 2; half++) {
            float mx = -1e30f;
            #pragma unroll
            for (int ni = 0; ni < 8; ni++)
                mx = fmaxf(mx, fmaxf(sacc[ni][2*half], sacc[ni][2*half+1]));
            mx = qreduce_max(mx);
            float mold = m_i[half];
            float mnew = fmaxf(mold, mx);
            float scale = __expf(mold - mnew);
            m_i[half] = mnew;

            int row = wm0 + grp + half * 8;
            float rsum = 0.0f;
            #pragma unroll
            for (int ni = 0; ni < 8; ni++) {
                float p0 = __expf(sacc[ni][2*half    ] - mnew);
                float p1 = __expf(sacc[ni][2*half + 1] - mnew);
                rsum += p0 + p1;
                *reinterpret_cast<float2*>(&sP[row * PS_STR + ni * 8 + 2 * tig]) =
                    make_float2(to_tf32(p0), to_tf32(p1));
            }
            rsum = qreduce_sum(rsum);
            l_i[half] = l_i[half] * scale + rsum;
            #pragma unroll
            for (int ni = 0; ni < 8; ni++) {
                oacc[ni][2*half    ] *= scale;
                oacc[ni][2*half + 1] *= scale;
            }
        }
        __syncwarp();

        // O += Ps @ Vs
        #pragma unroll
        for (int ks = 0; ks < 8; ks++) {
            const int kb = ks * 8;
            uint32_t af[4];
            af[0] = __float_as_uint(sP[(wm0 + grp    ) * PS_STR + kb + tig    ]);
            af[1] = __float_as_uint(sP[(wm0 + grp + 8) * PS_STR + kb + tig    ]);
            af[2] = __float_as_uint(sP[(wm0 + grp    ) * PS_STR + kb + tig + 4]);
            af[3] = __float_as_uint(sP[(wm0 + grp + 8) * PS_STR + kb + tig + 4]);
            #pragma unroll
            for (int ni = 0; ni < 8; ni++) {
                uint32_t bf[2];
                int c = ni * 8 + grp;
                bf[0] = __float_as_uint(sV[(kb + tig    ) * VS_STR + c]);
                bf[1] = __float_as_uint(sV[(kb + tig + 4) * VS_STR + c]);
                mma_tf32(oacc[ni], af, bf);
            }
        }
        __syncthreads();
    }

    // epilogue: O /= l, round to tf32 (feeds O-proj GEMM)
    float inv0 = 1.0f / l_i[0];
    float inv1 = 1.0f / l_i[1];
    long r0 = q0 + wm0 + grp;
    long r1 = r0 + 8;
    #pragma unroll
    for (int ni = 0; ni < 8; ni++) {
        int c0 = h * HD_DIM + ni * 8 + 2 * tig;
        *reinterpret_cast<float2*>(&o[r0 * D_DIM + c0]) =
            make_float2(to_tf32(oacc[ni][0] * inv0), to_tf32(oacc[ni][1] * inv0));
        *reinterpret_cast<float2*>(&o[r1 * D_DIM + c0]) =
            make_float2(to_tf32(oacc[ni][2] * inv1), to_tf32(oacc[ni][3] * inv1));
    }
}

// ---------------------------------------------------------------------------
// Launch
// ---------------------------------------------------------------------------
#define GEMM_SMEM ((2 * 128 * 36 + 2 * 32 * 136) * 4)          // 71680
#define FA_SMEM   ((FA_BQ * QS_STR + FA_BKV * KS_STR + FA_BKV * VS_STR + FA_BQ * PS_STR) * 4)

extern "C" void kernel_launch(void* const* d_in, const int* in_sizes, int n_in,
                              void* d_out, int out_size)
{
    const float* x    = (const float*)d_in[0];
    const float* ctx  = (const float*)d_in[1];
    const float* wq   = (const float*)d_in[2];
    const float* bq   = (const float*)d_in[3];
    const float* wk   = (const float*)d_in[4];
    const float* bk   = (const float*)d_in[5];
    const float* wv   = (const float*)d_in[6];
    const float* bv   = (const float*)d_in[7];
    const float* wo   = (const float*)d_in[8];
    const float* bo   = (const float*)d_in[9];
    const float* w1   = (const float*)d_in[10];
    const float* b1   = (const float*)d_in[11];
    const float* w2   = (const float*)d_in[12];
    const float* b2   = (const float*)d_in[13];
    const float* qn_w = (const float*)d_in[14];
    const float* qn_b = (const float*)d_in[15];
    const float* kvn_w= (const float*)d_in[16];
    const float* kvn_b= (const float*)d_in[17];
    const float* pn_w = (const float*)d_in[18];
    const float* pn_b = (const float*)d_in[19];
    float* out = (float*)d_out;

    float *xq, *kv, *q, *k, *v, *o, *x1, *hl, *h1;
    float *wqr, *wkr, *wvr, *wor, *w1r, *w2r;
    cudaGetSymbolAddress((void**)&xq, g_xq);
    cudaGetSymbolAddress((void**)&kv, g_kv);
    cudaGetSymbolAddress((void**)&q,  g_q);
    cudaGetSymbolAddress((void**)&k,  g_k);
    cudaGetSymbolAddress((void**)&v,  g_v);
    cudaGetSymbolAddress((void**)&o,  g_o);
    cudaGetSymbolAddress((void**)&x1, g_x1);
    cudaGetSymbolAddress((void**)&hl, g_hl);
    cudaGetSymbolAddress((void**)&h1, g_h1);
    cudaGetSymbolAddress((void**)&wqr, g_wq);
    cudaGetSymbolAddress((void**)&wkr, g_wk);
    cudaGetSymbolAddress((void**)&wvr, g_wv);
    cudaGetSymbolAddress((void**)&wor, g_wo);
    cudaGetSymbolAddress((void**)&w1r, g_w1);
    cudaGetSymbolAddress((void**)&w2r, g_w2);

    auto kProjR = mma_gemm<128,128,32,2,4,true,false,false,true>;   // ->tf32 out
    auto kRes   = mma_gemm<128,128,32,2,4,true,false,true,false>;   // full fp32 out
    auto kGeluR = mma_gemm<128,128,32,2,4,true,true,false,true>;    // ->tf32 out
    cudaFuncSetAttribute(kProjR, cudaFuncAttributeMaxDynamicSharedMemorySize, GEMM_SMEM);
    cudaFuncSetAttribute(kRes,   cudaFuncAttributeMaxDynamicSharedMemorySize, GEMM_SMEM);
    cudaFuncSetAttribute(kGeluR, cudaFuncAttributeMaxDynamicSharedMemorySize, GEMM_SMEM);
    cudaFuncSetAttribute(flash_attn, cudaFuncAttributeMaxDynamicSharedMemorySize, FA_SMEM);

    // 0) pre-round all weights to tf32 (epilogues pre-round activations)
    round_tf32_kernel<<<512, 256>>>(wq, wqr, D_DIM * D_DIM / 4);
    round_tf32_kernel<<<512, 256>>>(wk, wkr, C_DIM * D_DIM / 4);
    round_tf32_kernel<<<512, 256>>>(wv, wvr, C_DIM * D_DIM / 4);
    round_tf32_kernel<<<512, 256>>>(wo, wor, D_DIM * D_DIM / 4);
    round_tf32_kernel<<<512, 256>>>(w1, w1r, D_DIM * FF_DIM / 4);
    round_tf32_kernel<<<512, 256>>>(w2, w2r, FF_DIM * D_DIM / 4);

    // 1) pre-norms (tf32-rounded outputs)
    layernorm_kernel<<<N_TOK, 256>>>(x,   qn_w,  qn_b,  xq, D_DIM);
    layernorm_kernel<<<M_TOK, 256>>>(ctx, kvn_w, kvn_b, kv, C_DIM);

    // 2) Q/K/V projections (tf32-rounded outputs -> FA)
    {
        dim3 g(D_DIM / 128, N_TOK / 128, 1);
        kProjR<<<g, 256, GEMM_SMEM>>>(xq, wqr, bq, nullptr, q, D_DIM,
                                      D_DIM, D_DIM, D_DIM);
    }
    {
        dim3 g(D_DIM / 128, M_TOK / 128, 1);
        kProjR<<<g, 256, GEMM_SMEM>>>(kv, wkr, bk, nullptr, k, C_DIM,
                                      C_DIM, D_DIM, D_DIM);
        kProjR<<<g, 256, GEMM_SMEM>>>(kv, wvr, bv, nullptr, v, C_DIM,
                                      C_DIM, D_DIM, D_DIM);
    }

    // 3) fused attention
    {
        dim3 g(N_TOK / FA_BQ, H_HEADS, 1);
        flash_attn<<<g, 256, FA_SMEM>>>(q, k, v, o);
    }

    // 4) x1 = o @ wo + bo + x   (full fp32, residual)
    {
        dim3 g(D_DIM / 128, N_TOK / 128, 1);
        kRes<<<g, 256, GEMM_SMEM>>>(o, wor, bo, x, x1, D_DIM,
                                    D_DIM, D_DIM, D_DIM);
    }
    // 5) hl = LN(x1)  (tf32-rounded)
    layernorm_kernel<<<N_TOK, 256>>>(x1, pn_w, pn_b, hl, D_DIM);

    // 6) h1 = gelu(hl @ w1 + b1)  (tf32-rounded)
    {
        dim3 g(FF_DIM / 128, N_TOK / 128, 1);
        kGeluR<<<g, 256, GEMM_SMEM>>>(hl, w1r, b1, nullptr, h1, D_DIM,
                                      D_DIM, FF_DIM, FF_DIM);
    }
    // 7) out = h1 @ w2 + b2 + x1  (full fp32)
    {
        dim3 g(D_DIM / 128, N_TOK / 128, 1);
        kRes<<<g, 256, GEMM_SMEM>>>(h1, w2r, b2, x1, out, FF_DIM,
                                    FF_DIM, D_DIM, D_DIM);
    }
}